// round 2
// baseline (speedup 1.0000x reference)
#include <cuda_runtime.h>
#include <cstdint>

#define BATCH 64
#define TLEN  512
#define D     1024

// ---------------- scratch (device globals: no allocations allowed) ----------------
__device__ float g_ext[(size_t)BATCH * TLEN * D];   // 128 MB: input projections
__device__ float g_stateA[BATCH * D];
__device__ float g_stateB[BATCH * D];

// ---------------- packed f32x2 helpers (sm_103a FFMA2 path) ----------------
static __device__ __forceinline__ unsigned long long pack_dup(float w) {
    unsigned long long r;
    asm("mov.b64 %0, {%1, %1};" : "=l"(r) : "f"(w));
    return r;
}
static __device__ __forceinline__ void fma2(unsigned long long& d,
                                            unsigned long long a,
                                            unsigned long long b) {
    asm("fma.rn.f32x2 %0, %1, %2, %0;" : "+l"(d) : "l"(a), "l"(b));
}
static __device__ __forceinline__ void unpack2(unsigned long long v, float& lo, float& hi) {
    asm("mov.b64 {%0, %1}, %2;" : "=f"(lo), "=f"(hi) : "l"(v));
}

// ---------------- trivial zero kernels ----------------
__global__ void zero4_kernel(float4* __restrict__ p, int n4) {
    int i = blockIdx.x * blockDim.x + threadIdx.x;
    if (i < n4) p[i] = make_float4(0.f, 0.f, 0.f, 0.f);
}
__global__ void zero_state_kernel() {
    int i = blockIdx.x * blockDim.x + threadIdx.x;
    if (i < BATCH * D) g_stateA[i] = 0.f;
}

// ---------------- Phase A: ext[m][n] = sum_k x[m][k] * W_in[n][k] ----------------
// M=32768, N=1024, K=1024. Tiles: BM=128, BN=64, BK=32; 256 threads, 8m x 4n per
// thread, accumulators packed over m-pairs (f32x2).
#define BM 128
#define BN 64
#define BK 32
#define PADA 134   // keeps 8B alignment for ull loads, ~2-way store conflicts
#define PADB 68    // keeps 16B alignment for float4 loads

__global__ __launch_bounds__(256) void ext_gemm_kernel(const float* __restrict__ X,
                                                       const float* __restrict__ Win) {
    __shared__ float As[BK * PADA];   // transposed: As[k][m]
    __shared__ float Bs[BK * PADB];   // transposed: Bs[k][n]

    const int tid = threadIdx.x;
    const int Mb = blockIdx.y * BM;
    const int Nb = blockIdx.x * BN;
    const int ty = tid >> 4, tx = tid & 15;
    const int m0 = ty * 8, n0 = tx * 4;

    unsigned long long acc[4][4];
#pragma unroll
    for (int i = 0; i < 4; ++i)
#pragma unroll
        for (int j = 0; j < 4; ++j) acc[i][j] = 0ULL;

    const int ar = tid >> 3, ac = tid & 7;   // A loader
    const int br = tid >> 2, bc = tid & 3;   // B loader

    for (int kt = 0; kt < D / BK; ++kt) {
        const int k0 = kt * BK;
#pragma unroll
        for (int g = 0; g < 4; ++g) {
            const int m = ar + g * 32;
            float4 v = *(const float4*)&X[(size_t)(Mb + m) * D + k0 + ac * 4];
            As[(ac * 4 + 0) * PADA + m] = v.x;
            As[(ac * 4 + 1) * PADA + m] = v.y;
            As[(ac * 4 + 2) * PADA + m] = v.z;
            As[(ac * 4 + 3) * PADA + m] = v.w;
        }
#pragma unroll
        for (int g = 0; g < 2; ++g) {
            const int cc = bc + g * 4;
            float4 v = *(const float4*)&Win[(size_t)(Nb + br) * D + k0 + cc * 4];
            Bs[(cc * 4 + 0) * PADB + br] = v.x;
            Bs[(cc * 4 + 1) * PADB + br] = v.y;
            Bs[(cc * 4 + 2) * PADB + br] = v.z;
            Bs[(cc * 4 + 3) * PADB + br] = v.w;
        }
        __syncthreads();

#pragma unroll
        for (int kk = 0; kk < BK; ++kk) {
            const float* asr = &As[kk * PADA + m0];
            unsigned long long a0 = *(const unsigned long long*)(asr + 0);
            unsigned long long a1 = *(const unsigned long long*)(asr + 2);
            unsigned long long a2 = *(const unsigned long long*)(asr + 4);
            unsigned long long a3 = *(const unsigned long long*)(asr + 6);
            float4 bv = *(const float4*)&Bs[kk * PADB + n0];
            unsigned long long b0 = pack_dup(bv.x);
            unsigned long long b1 = pack_dup(bv.y);
            unsigned long long b2 = pack_dup(bv.z);
            unsigned long long b3 = pack_dup(bv.w);
            fma2(acc[0][0], a0, b0); fma2(acc[0][1], a0, b1); fma2(acc[0][2], a0, b2); fma2(acc[0][3], a0, b3);
            fma2(acc[1][0], a1, b0); fma2(acc[1][1], a1, b1); fma2(acc[1][2], a1, b2); fma2(acc[1][3], a1, b3);
            fma2(acc[2][0], a2, b0); fma2(acc[2][1], a2, b1); fma2(acc[2][2], a2, b2); fma2(acc[2][3], a2, b3);
            fma2(acc[3][0], a3, b0); fma2(acc[3][1], a3, b1); fma2(acc[3][2], a3, b2); fma2(acc[3][3], a3, b3);
        }
        __syncthreads();
    }

#pragma unroll
    for (int i = 0; i < 4; ++i) {
        float lo[4], hi[4];
#pragma unroll
        for (int j = 0; j < 4; ++j) unpack2(acc[i][j], lo[j], hi[j]);
        const int m = Mb + m0 + 2 * i;
        *(float4*)&g_ext[(size_t)m * D + Nb + n0]       = make_float4(lo[0], lo[1], lo[2], lo[3]);
        *(float4*)&g_ext[(size_t)(m + 1) * D + Nb + n0] = make_float4(hi[0], hi[1], hi[2], hi[3]);
    }
}

// ---------------- Phase B: one recurrence step ----------------
// new_state[b][o] = relu( sum_k (state[b][k] + ext[b][t][k]) * W_rec[o][k] )
// Grid (64, 2): N-tile 16, M-tile 32.  512 threads = 16 warps, each warp owns a
// 64-wide K slice (in-CTA K-split) so each thread computes 4m x 4n outputs with
// f32x2-packed accumulators. Partial sums reduced through smem at the end.
#define MT 32
#define NT 16
#define PADS 34
#define PADW 18
#define STEP_SMEM ((D * PADW + D * PADS) * 4)   // 212992 B

__global__ __launch_bounds__(512) void step_kernel(const float* __restrict__ Wr, int t) {
    extern __shared__ float sm[];
    float* WT = sm;                 // WT[k][n], D x PADW
    float* sT = sm + D * PADW;      // sT[k][m], D x PADS
    float* red = sT;                // aliased after compute

    const float* sin = (t & 1) ? g_stateB : g_stateA;
    float* sout      = (t & 1) ? g_stateA : g_stateB;

    const int tid = threadIdx.x;
    const int Nb = blockIdx.x * NT;
    const int Mb = blockIdx.y * MT;

    // load s = state + ext_t (transposed into sT)
    {
        const int m = tid >> 4;        // 0..31
        const int c0 = tid & 15;
        const int gm = Mb + m;
        const float* srow = sin + (size_t)gm * D;
        const float* erow = g_ext + (size_t)gm * (TLEN * D) + (size_t)t * D;
#pragma unroll
        for (int j = 0; j < 16; ++j) {
            const int c = c0 + j * 16;
            float4 a = *(const float4*)&srow[c * 4];
            float4 b = *(const float4*)&erow[c * 4];
            const int k = c * 4;
            sT[(k + 0) * PADS + m] = a.x + b.x;
            sT[(k + 1) * PADS + m] = a.y + b.y;
            sT[(k + 2) * PADS + m] = a.z + b.z;
            sT[(k + 3) * PADS + m] = a.w + b.w;
        }
    }
    // load W tile (transposed into WT)
    {
        const int n = tid >> 5;        // 0..15
        const int c0 = tid & 31;
        const float* wrow = Wr + (size_t)(Nb + n) * D;
#pragma unroll
        for (int j = 0; j < 8; ++j) {
            const int c = c0 + j * 32;
            float4 v = *(const float4*)&wrow[c * 4];
            const int k = c * 4;
            WT[(k + 0) * PADW + n] = v.x;
            WT[(k + 1) * PADW + n] = v.y;
            WT[(k + 2) * PADW + n] = v.z;
            WT[(k + 3) * PADW + n] = v.w;
        }
    }
    __syncthreads();

    const int w = tid >> 5, lane = tid & 31;
    const int mi = lane >> 2, ni = lane & 3;
    const int m0 = mi * 4, n0 = ni * 4;
    unsigned long long acc[8];
#pragma unroll
    for (int i = 0; i < 8; ++i) acc[i] = 0ULL;

    const int kbeg = w * 64;
#pragma unroll 8
    for (int kk = kbeg; kk < kbeg + 64; ++kk) {
        const float* sr = &sT[kk * PADS + m0];
        unsigned long long a0 = *(const unsigned long long*)(sr + 0);
        unsigned long long a1 = *(const unsigned long long*)(sr + 2);
        float2 w01 = *(const float2*)&WT[kk * PADW + n0];
        float2 w23 = *(const float2*)&WT[kk * PADW + n0 + 2];
        unsigned long long b0 = pack_dup(w01.x);
        unsigned long long b1 = pack_dup(w01.y);
        unsigned long long b2 = pack_dup(w23.x);
        unsigned long long b3 = pack_dup(w23.y);
        fma2(acc[0], a0, b0); fma2(acc[1], a0, b1); fma2(acc[2], a0, b2); fma2(acc[3], a0, b3);
        fma2(acc[4], a1, b0); fma2(acc[5], a1, b1); fma2(acc[6], a1, b2); fma2(acc[7], a1, b3);
    }
    __syncthreads();   // all sT reads done before aliasing as `red`

#pragma unroll
    for (int j = 0; j < 4; ++j) {
        float lo, hi;
        unpack2(acc[j], lo, hi);
        red[w * 512 + (m0 + 0) * 16 + n0 + j] = lo;
        red[w * 512 + (m0 + 1) * 16 + n0 + j] = hi;
        unpack2(acc[4 + j], lo, hi);
        red[w * 512 + (m0 + 2) * 16 + n0 + j] = lo;
        red[w * 512 + (m0 + 3) * 16 + n0 + j] = hi;
    }
    __syncthreads();

    {
        const int o = tid;             // 0..511
        float sum = 0.f;
#pragma unroll
        for (int g = 0; g < 16; ++g) sum += red[g * 512 + o];
        sum = fmaxf(sum, 0.f);
        const int m = o >> 4, n = o & 15;
        sout[(size_t)(Mb + m) * D + Nb + n] = sum;
    }
}

// ---------------- final: out[:,0,:] = final state ----------------
__global__ void final_copy_kernel(float* __restrict__ out) {
    const int i = blockIdx.x * blockDim.x + threadIdx.x;   // < 65536
    const int b = i >> 10, o = i & 1023;
    out[(size_t)b * (TLEN * D) + o] = g_stateA[i];
}

// ---------------- launch ----------------
extern "C" void kernel_launch(void* const* d_in, const int* in_sizes, int n_in,
                              void* d_out, int out_size) {
    const float* x     = (const float*)d_in[0];
    const float* W_in  = (const float*)d_in[1];
    const float* W_rec = (const float*)d_in[2];
    float* out = (float*)d_out;

    cudaFuncSetAttribute(step_kernel, cudaFuncAttributeMaxDynamicSharedMemorySize, STEP_SMEM);

    // zero output (poisoned by harness) and initial state
    zero4_kernel<<<(BATCH * TLEN * D / 4 + 255) / 256, 256>>>((float4*)out, BATCH * TLEN * D / 4);
    zero_state_kernel<<<(BATCH * D + 255) / 256, 256>>>();

    // Phase A: input projections for all timesteps
    ext_gemm_kernel<<<dim3(D / BN, (BATCH * TLEN) / BM), 256>>>(x, W_in);

    // Phase B: sequential recurrence
    for (int t = 0; t < TLEN; ++t) {
        step_kernel<<<dim3(D / NT, BATCH / MT), 512, STEP_SMEM>>>(W_rec, t);
    }

    // write final state into out[:,0,:]
    final_copy_kernel<<<(BATCH * D) / 256, 256>>>(out);
}

// round 3
// speedup vs baseline: 1.5092x; 1.5092x over previous
#include <cuda_runtime.h>
#include <cstdint>

#define BATCH 64
#define TLEN  512
#define D     1024

// ---------------- scratch (device globals: no allocations allowed) ----------------
__device__ float g_ext[(size_t)BATCH * TLEN * D];   // 128 MB: input projections
__device__ float g_stateA[BATCH * D];
__device__ float g_stateB[BATCH * D];
__device__ unsigned g_bar;                           // grid barrier counter

// ---------------- packed f32x2 helpers (sm_103a FFMA2 path) ----------------
static __device__ __forceinline__ unsigned long long pack_dup(float w) {
    unsigned long long r;
    asm("mov.b64 %0, {%1, %1};" : "=l"(r) : "f"(w));
    return r;
}
static __device__ __forceinline__ void fma2(unsigned long long& d,
                                            unsigned long long a,
                                            unsigned long long b) {
    asm("fma.rn.f32x2 %0, %1, %2, %0;" : "+l"(d) : "l"(a), "l"(b));
}
static __device__ __forceinline__ void unpack2(unsigned long long v, float& lo, float& hi) {
    asm("mov.b64 {%0, %1}, %2;" : "=f"(lo), "=f"(hi) : "l"(v));
}

// ---------------- trivial zero kernels ----------------
__global__ void zero4_kernel(float4* __restrict__ p, int n4) {
    int i = blockIdx.x * blockDim.x + threadIdx.x;
    if (i < n4) p[i] = make_float4(0.f, 0.f, 0.f, 0.f);
}
__global__ void zero_state_kernel() {
    int i = blockIdx.x * blockDim.x + threadIdx.x;
    if (i < BATCH * D) g_stateA[i] = 0.f;
    if (i == 0) g_bar = 0u;
}

// ---------------- Phase A: ext[m][n] = sum_k x[m][k] * W_in[n][k] ----------------
#define BM 128
#define BN 64
#define BK 32
#define PADA 134
#define PADB 68

__global__ __launch_bounds__(256) void ext_gemm_kernel(const float* __restrict__ X,
                                                       const float* __restrict__ Win) {
    __shared__ float As[BK * PADA];   // As[k][m]
    __shared__ float Bs[BK * PADB];   // Bs[k][n]

    const int tid = threadIdx.x;
    const int Mb = blockIdx.y * BM;
    const int Nb = blockIdx.x * BN;
    const int ty = tid >> 4, tx = tid & 15;
    const int m0 = ty * 8, n0 = tx * 4;

    unsigned long long acc[4][4];
#pragma unroll
    for (int i = 0; i < 4; ++i)
#pragma unroll
        for (int j = 0; j < 4; ++j) acc[i][j] = 0ULL;

    const int ar = tid >> 3, ac = tid & 7;
    const int br = tid >> 2, bc = tid & 3;

    for (int kt = 0; kt < D / BK; ++kt) {
        const int k0 = kt * BK;
#pragma unroll
        for (int g = 0; g < 4; ++g) {
            const int m = ar + g * 32;
            float4 v = *(const float4*)&X[(size_t)(Mb + m) * D + k0 + ac * 4];
            As[(ac * 4 + 0) * PADA + m] = v.x;
            As[(ac * 4 + 1) * PADA + m] = v.y;
            As[(ac * 4 + 2) * PADA + m] = v.z;
            As[(ac * 4 + 3) * PADA + m] = v.w;
        }
#pragma unroll
        for (int g = 0; g < 2; ++g) {
            const int cc = bc + g * 4;
            float4 v = *(const float4*)&Win[(size_t)(Nb + br) * D + k0 + cc * 4];
            Bs[(cc * 4 + 0) * PADB + br] = v.x;
            Bs[(cc * 4 + 1) * PADB + br] = v.y;
            Bs[(cc * 4 + 2) * PADB + br] = v.z;
            Bs[(cc * 4 + 3) * PADB + br] = v.w;
        }
        __syncthreads();

#pragma unroll
        for (int kk = 0; kk < BK; ++kk) {
            const float* asr = &As[kk * PADA + m0];
            unsigned long long a0 = *(const unsigned long long*)(asr + 0);
            unsigned long long a1 = *(const unsigned long long*)(asr + 2);
            unsigned long long a2 = *(const unsigned long long*)(asr + 4);
            unsigned long long a3 = *(const unsigned long long*)(asr + 6);
            float4 bv = *(const float4*)&Bs[kk * PADB + n0];
            unsigned long long b0 = pack_dup(bv.x);
            unsigned long long b1 = pack_dup(bv.y);
            unsigned long long b2 = pack_dup(bv.z);
            unsigned long long b3 = pack_dup(bv.w);
            fma2(acc[0][0], a0, b0); fma2(acc[0][1], a0, b1); fma2(acc[0][2], a0, b2); fma2(acc[0][3], a0, b3);
            fma2(acc[1][0], a1, b0); fma2(acc[1][1], a1, b1); fma2(acc[1][2], a1, b2); fma2(acc[1][3], a1, b3);
            fma2(acc[2][0], a2, b0); fma2(acc[2][1], a2, b1); fma2(acc[2][2], a2, b2); fma2(acc[2][3], a2, b3);
            fma2(acc[3][0], a3, b0); fma2(acc[3][1], a3, b1); fma2(acc[3][2], a3, b2); fma2(acc[3][3], a3, b3);
        }
        __syncthreads();
    }

#pragma unroll
    for (int i = 0; i < 4; ++i) {
        float lo[4], hi[4];
#pragma unroll
        for (int j = 0; j < 4; ++j) unpack2(acc[i][j], lo[j], hi[j]);
        const int m = Mb + m0 + 2 * i;
        *(float4*)&g_ext[(size_t)m * D + Nb + n0]       = make_float4(lo[0], lo[1], lo[2], lo[3]);
        *(float4*)&g_ext[(size_t)(m + 1) * D + Nb + n0] = make_float4(hi[0], hi[1], hi[2], hi[3]);
    }
}

// ---------------- Phase B: persistent recurrence kernel ----------------
// Grid (32 n-tiles, 4 m-tiles) = 128 CTAs, 512 threads. W_rec n-slice (32x1024)
// stays resident in smem for all 512 steps. Per step: load s = state+ext tile
// (16x1024) into smem, 16-way k-split GEMM with k-pair-packed FFMA2, smem
// reduction, write new state, grid-wide spin barrier.
#define NTILE 32
#define MTILE 16
#define ROWST 1028                       // floats; 16B-aligned, bank inc 4/row
#define PERS_SMEM ((NTILE + MTILE) * ROWST * 4)   // 197376 B

__global__ __launch_bounds__(512, 1) void rnn_persistent(const float* __restrict__ Wr) {
    extern __shared__ float sm[];
    float* Wsm = sm;                       // [32][ROWST]
    float* sT  = sm + NTILE * ROWST;       // [16][ROWST]
    unsigned long long* red = (unsigned long long*)sT;   // aliased: [16][512]

    const int tid = threadIdx.x;
    const int Nb = blockIdx.x * NTILE;
    const int Mb = blockIdx.y * MTILE;

    // ---- load W slice once (resident for all steps) ----
    {
        const int n = tid >> 4, c = tid & 15;
        const float* wrow = Wr + (size_t)(Nb + n) * D;
        float* dst = Wsm + n * ROWST;
#pragma unroll
        for (int j = 0; j < 16; ++j) {
            const int q = c + j * 16;
            *(float4*)&dst[q * 4] = *(const float4*)&wrow[q * 4];
        }
    }

    // compute-phase decomposition: warp = k-group
    const int kg = tid >> 5;               // 0..15, 64 k each
    const int lane = tid & 31;
    const int mi = lane & 3;               // m rows: mi, mi+4, mi+8, mi+12
    const int ni = lane >> 2;              // n rows: ni, ni+8, ni+16, ni+24
    const int k0 = kg * 64;

    // load/reduce-phase decomposition
    const int lm = tid >> 5;               // 0..15 (row)
    const int lc = tid & 31;               // 0..31

    for (int t = 0; t < TLEN; ++t) {
        const float* sin = (t & 1) ? g_stateB : g_stateA;
        float* sout      = (t & 1) ? g_stateA : g_stateB;

        // ---- load s-tile = state + ext[t] (row-major, stride ROWST) ----
        {
            const float4* srow = (const float4*)(sin + (size_t)(Mb + lm) * D);
            const float4* erow = (const float4*)(g_ext + (size_t)(Mb + lm) * (TLEN * D) + (size_t)t * D);
            float* dst = sT + lm * ROWST;
#pragma unroll
            for (int j = 0; j < 8; ++j) {
                const int q = lc + j * 32;
                float4 a = __ldcg(srow + q);      // bypass L1: state is cross-SM dynamic
                float4 b = __ldg(erow + q);       // ext is immutable
                *(float4*)&dst[q * 4] = make_float4(a.x + b.x, a.y + b.y, a.z + b.z, a.w + b.w);
            }
        }
        __syncthreads();

        // ---- compute: 4m x 4n per thread over 64 k (k-pair packed FFMA2) ----
        unsigned long long acc[16];
#pragma unroll
        for (int i = 0; i < 16; ++i) acc[i] = 0ULL;

        const float* aBase = sT + (size_t)mi * ROWST + k0;
        const float* bBase = Wsm + (size_t)ni * ROWST + k0;

#pragma unroll 8
        for (int it = 0; it < 16; ++it) {
            const int k = it * 4;
            ulonglong2 av[4], bv[4];
#pragma unroll
            for (int r = 0; r < 4; ++r)
                av[r] = *(const ulonglong2*)(aBase + r * (4 * ROWST) + k);
#pragma unroll
            for (int c = 0; c < 4; ++c)
                bv[c] = *(const ulonglong2*)(bBase + c * (8 * ROWST) + k);
#pragma unroll
            for (int r = 0; r < 4; ++r)
#pragma unroll
                for (int c = 0; c < 4; ++c) {
                    fma2(acc[r * 4 + c], av[r].x, bv[c].x);
                    fma2(acc[r * 4 + c], av[r].y, bv[c].y);
                }
        }
        __syncthreads();   // all sT reads done before aliasing as red

        // ---- store k-group partials (swizzled to cut bank conflicts) ----
#pragma unroll
        for (int r = 0; r < 4; ++r)
#pragma unroll
            for (int c = 0; c < 4; ++c) {
                const int m = mi + 4 * r, n = ni + 8 * c;
                red[kg * 512 + m * 32 + (n ^ (mi << 2))] = acc[r * 4 + c];
            }
        __syncthreads();

        // ---- reduce 16 partials, ReLU, write new state ----
        {
            const int m = lm, n = lc;
            const int idx = m * 32 + (n ^ ((m & 3) << 2));
            float lo = 0.f, hi = 0.f;
#pragma unroll
            for (int g = 0; g < 16; ++g) {
                float2 v = *(const float2*)&red[g * 512 + idx];
                lo += v.x; hi += v.y;
            }
            sout[(size_t)(Mb + m) * D + (Nb + n)] = fmaxf(lo + hi, 0.f);
        }

        // ---- grid-wide barrier (all 128 CTAs co-resident: 1 CTA/SM) ----
        __syncthreads();
        if (tid == 0) {
            __threadfence();                         // release this CTA's state writes
            atomicAdd(&g_bar, 1u);
            const unsigned target = 128u * (unsigned)(t + 1);
            unsigned v;
            do {
                asm volatile("ld.acquire.gpu.u32 %0, [%1];" : "=r"(v) : "l"(&g_bar));
            } while (v < target);
        }
        __syncthreads();
    }
}

// ---------------- final: out[:,0,:] = final state ----------------
__global__ void final_copy_kernel(float* __restrict__ out) {
    const int i = blockIdx.x * blockDim.x + threadIdx.x;   // < 65536
    const int b = i >> 10, o = i & 1023;
    out[(size_t)b * (TLEN * D) + o] = g_stateA[i];
}

// ---------------- launch ----------------
extern "C" void kernel_launch(void* const* d_in, const int* in_sizes, int n_in,
                              void* d_out, int out_size) {
    const float* x     = (const float*)d_in[0];
    const float* W_in  = (const float*)d_in[1];
    const float* W_rec = (const float*)d_in[2];
    float* out = (float*)d_out;

    cudaFuncSetAttribute(rnn_persistent, cudaFuncAttributeMaxDynamicSharedMemorySize, PERS_SMEM);

    // zero output (poisoned by harness), initial state, barrier counter
    zero4_kernel<<<(BATCH * TLEN * D / 4 + 255) / 256, 256>>>((float4*)out, BATCH * TLEN * D / 4);
    zero_state_kernel<<<(BATCH * D + 255) / 256, 256>>>();

    // Phase A: input projections for all timesteps
    ext_gemm_kernel<<<dim3(D / BN, (BATCH * TLEN) / BM), 256>>>(x, W_in);

    // Phase B: full recurrence in one persistent kernel
    rnn_persistent<<<dim3(D / NTILE, BATCH / MTILE), 512, PERS_SMEM>>>(W_rec);

    // write final state into out[:,0,:]
    final_copy_kernel<<<(BATCH * D) / 256, 256>>>(out);
}